// round 5
// baseline (speedup 1.0000x reference)
#include <cuda_runtime.h>
#include <math_constants.h>

#define BB 4
#define TT 4096
#define DD 1024
#define NROW (BB*TT)          // 16384

// ---- scratch (device globals: no allocations allowed) ----
__device__ float2 g_Q[NROW];
__device__ float2 g_K[NROW];
__device__ unsigned long long g_best64[NROW]; // (ordered(score)<<32)|~s
__device__ int    g_idx[NROW];      // flattened source row b*T + argmax_s
__device__ int    g_mark[NROW];
__device__ int    g_slot[NROW];     // src row -> compact slot
__device__ int    g_list[NROW];
__device__ int    g_count;
__device__ float  g_Vc[(size_t)NROW * DD];  // compact V rows (slot-major)

static const unsigned FULL = 0xffffffffu;

__device__ __forceinline__ unsigned ord_f32(float x) {
    unsigned u = __float_as_uint(x);
    return (u & 0x80000000u) ? ~u : (u | 0x80000000u);
}

// ---------------- kernel 1: Q,K projection (+ fused scratch init) ----------
__global__ void qk_kernel(const float* __restrict__ x,
                          const float* __restrict__ WQ,
                          const float* __restrict__ WK) {
    __shared__ float4 swq0[256], swq1[256], swk0[256], swk1[256];
    const float4* WQ4 = (const float4*)WQ;
    const float4* WK4 = (const float4*)WK;
    int tid = threadIdx.x;
    swq0[tid] = WQ4[tid];
    swq1[tid] = WQ4[256 + tid];
    swk0[tid] = WK4[tid];
    swk1[tid] = WK4[256 + tid];
    __syncthreads();

    int warp = tid >> 5, lane = tid & 31;
    int row = blockIdx.x * 8 + warp;           // b*T + t
    const float4* x4 = (const float4*)x + (size_t)row * 256;

    float q0 = 0.f, q1 = 0.f, k0 = 0.f, k1 = 0.f;
#pragma unroll
    for (int j = 0; j < 8; ++j) {
        int d = lane + j * 32;
        float4 xv = x4[d];
        float4 a = swq0[d], b = swq1[d], c = swk0[d], e = swk1[d];
        q0 += xv.x*a.x + xv.y*a.y + xv.z*a.z + xv.w*a.w;
        q1 += xv.x*b.x + xv.y*b.y + xv.z*b.z + xv.w*b.w;
        k0 += xv.x*c.x + xv.y*c.y + xv.z*c.z + xv.w*c.w;
        k1 += xv.x*e.x + xv.y*e.y + xv.z*e.z + xv.w*e.w;
    }
#pragma unroll
    for (int off = 16; off; off >>= 1) {
        q0 += __shfl_xor_sync(FULL, q0, off);
        q1 += __shfl_xor_sync(FULL, q1, off);
        k0 += __shfl_xor_sync(FULL, k0, off);
        k1 += __shfl_xor_sync(FULL, k1, off);
    }
    if (lane == 0) {
        g_Q[row] = make_float2(q0, q1);
        g_K[row] = make_float2(k0, k1);
        g_mark[row] = 0;
        g_best64[row] = 0ull;                  // < any real score encoding
        if (row == 0) g_count = 0;
    }
}

// ---------------- kernel 2: argmax, tile x chunk units ----------------
// Unit = (128-t tile, 1024-s chunk). 80 units/batch, grid (80, BB), 128 thr.
// Merge via atomicMax of (ordered(score)<<32)|~s  -> max score, min s on tie.
__global__ void __launch_bounds__(128) argmax_kernel() {
    __shared__ float2 ks[1024];    // 8 KB
    int b = blockIdx.y;
    int u = blockIdx.x, g = 0, base = 0;
    while (u >= base + 8 * (g + 1)) { base += 8 * (g + 1); ++g; }
    int r = u - base;
    int ti = g * 8 + r / (g + 1);
    int chunk = r % (g + 1);
    int t0 = ti * 128, s0 = chunk * 1024;

    const float4* K4 = (const float4*)(g_K + b * TT + s0);
#pragma unroll
    for (int j = 0; j < 4; ++j)
        ((float4*)ks)[threadIdx.x + j * 128] = K4[threadIdx.x + j * 128];
    __syncthreads();

    int t = t0 + threadIdx.x;
    float2 q = g_Q[b * TT + t];
    int s_limit = t - s0 + 1;
    if (s_limit > 1024) s_limit = 1024;

    float best = -CUDART_INF_F;
    int bi = 0;
    for (int s = 0; s < s_limit; ++s) {        // ascending + strict > = first occ.
        float2 k = ks[s];
        float sc = k.x * q.x + k.y * q.y;
        if (sc > best) { best = sc; bi = s0 + s; }
    }
    unsigned long long enc =
        ((unsigned long long)ord_f32(best) << 32) | (unsigned)(~bi);
    atomicMax(&g_best64[b * TT + t], enc);
}

// ---------------- kernel 2b: decode argmax + build unique list -------------
__global__ void decode_kernel() {
    int i = blockIdx.x * 256 + threadIdx.x;
    if (i >= NROW) return;
    unsigned long long enc = g_best64[i];
    int s = (int)(~(unsigned)(enc & 0xffffffffull));
    int src = (i & ~(TT - 1)) | s;
    g_idx[i] = src;
    if (atomicExch(&g_mark[src], 1) == 0) {
        int p = atomicAdd(&g_count, 1);
        g_list[p] = src;
        g_slot[src] = p;                       // read only by later kernels
    }
}

// ---------------- kernel 3: V rows, W_V-stationary + ILP ----------------
// 128 blocks; block stages 8 e-rows of W_V in smem ONCE (32 KB -> total W_V
// traffic 4 MB). Warps stride over unique rows; per row: x -> registers,
// 2 x (4 simultaneous e-accumulators) with interleaved shuffle reduces.
// Output compact: row with list-position ui goes to slot ui.
#define E_PER_BLK 8
__global__ void __launch_bounds__(256) vrows_kernel(const float* __restrict__ WV,
                                                    const float* __restrict__ x) {
    __shared__ float4 wv_s[E_PER_BLK * 256];   // 32 KB
    int eb = blockIdx.x * E_PER_BLK;
    for (int i = threadIdx.x; i < E_PER_BLK * 256; i += 256)
        wv_s[i] = ((const float4*)WV)[(size_t)eb * 256 + i];
    __syncthreads();

    int cnt = g_count;
    int warp = threadIdx.x >> 5, lane = threadIdx.x & 31;

    for (int ui = warp; ui < cnt; ui += 8) {
        int row = g_list[ui];
        const float4* xr = (const float4*)x + (size_t)row * 256;
        float4 xv[8];
#pragma unroll
        for (int j = 0; j < 8; ++j)
            xv[j] = __ldg(&xr[lane + j * 32]);

#pragma unroll
        for (int eg = 0; eg < 2; ++eg) {
            const float4* s0 = &wv_s[(eg * 4 + 0) * 256];
            const float4* s1 = &wv_s[(eg * 4 + 1) * 256];
            const float4* s2 = &wv_s[(eg * 4 + 2) * 256];
            const float4* s3 = &wv_s[(eg * 4 + 3) * 256];
            float a0 = 0.f, a1 = 0.f, a2 = 0.f, a3 = 0.f;
#pragma unroll
            for (int j = 0; j < 8; ++j) {
                int d = lane + j * 32;
                float4 w0 = s0[d], w1 = s1[d], w2 = s2[d], w3 = s3[d];
                a0 += w0.x*xv[j].x + w0.y*xv[j].y + w0.z*xv[j].z + w0.w*xv[j].w;
                a1 += w1.x*xv[j].x + w1.y*xv[j].y + w1.z*xv[j].z + w1.w*xv[j].w;
                a2 += w2.x*xv[j].x + w2.y*xv[j].y + w2.z*xv[j].z + w2.w*xv[j].w;
                a3 += w3.x*xv[j].x + w3.y*xv[j].y + w3.z*xv[j].z + w3.w*xv[j].w;
            }
#pragma unroll
            for (int off = 16; off; off >>= 1) {
                a0 += __shfl_xor_sync(FULL, a0, off);
                a1 += __shfl_xor_sync(FULL, a1, off);
                a2 += __shfl_xor_sync(FULL, a2, off);
                a3 += __shfl_xor_sync(FULL, a3, off);
            }
            if (lane == 0) {
                float* dst = g_Vc + (size_t)ui * DD + eb + eg * 4;
                dst[0] = a0; dst[1] = a1; dst[2] = a2; dst[3] = a3;
            }
        }
    }
}

// ---------------- kernel 4: gather to output ----------------
// Warp copies one 4KB row from compact (L2-resident) V; streaming stores.
__global__ void gather_kernel(float* __restrict__ out) {
    int warp = threadIdx.x >> 5, lane = threadIdx.x & 31;
    int r = blockIdx.x * 8 + warp;          // destination row b*T + t
    int slot = g_slot[g_idx[r]];
    const float4* v4 = (const float4*)g_Vc + (size_t)slot * 256;
    float4* o4 = (float4*)out + (size_t)r * 256;
#pragma unroll
    for (int j = 0; j < 8; ++j) {
        float4 v = __ldg(&v4[lane + j * 32]);
        __stcs(&o4[lane + j * 32], v);
    }
}

extern "C" void kernel_launch(void* const* d_in, const int* in_sizes, int n_in,
                              void* d_out, int out_size) {
    const float* x  = (const float*)d_in[0];
    const float* WQ = (const float*)d_in[1];
    const float* WK = (const float*)d_in[2];
    const float* WV = (const float*)d_in[3];
    float* out = (float*)d_out;

    qk_kernel<<<NROW / 8, 256>>>(x, WQ, WK);
    argmax_kernel<<<dim3(80, BB), 128>>>();
    decode_kernel<<<NROW / 256, 256>>>();
    vrows_kernel<<<DD / E_PER_BLK, 256>>>(WV, x);
    gather_kernel<<<NROW / 8, 256>>>(out);
}

// round 6
// speedup vs baseline: 1.2737x; 1.2737x over previous
#include <cuda_runtime.h>
#include <math_constants.h>

#define BB 4
#define TT 4096
#define DD 1024
#define NROW (BB*TT)          // 16384

// ---- scratch (device globals: no allocations allowed) ----
__device__ float2 g_Q[NROW];
__device__ float2 g_K[NROW];
__device__ unsigned long long g_best64[NROW]; // (ordered(score)<<32)|~s
__device__ int    g_idx[NROW];      // flattened source row b*T + argmax_s
__device__ int    g_mark[NROW];
__device__ int    g_slot[NROW];     // src row -> compact slot
__device__ int    g_list[NROW];
__device__ int    g_count;
__device__ float  g_Vc[(size_t)NROW * DD];  // compact V rows (slot-major)

static const unsigned FULL = 0xffffffffu;

__device__ __forceinline__ unsigned ord_f32(float x) {
    unsigned u = __float_as_uint(x);
    return (u & 0x80000000u) ? ~u : (u | 0x80000000u);
}

// ---------------- kernel 1: Q,K projection (+ fused scratch init) ----------
__global__ void qk_kernel(const float* __restrict__ x,
                          const float* __restrict__ WQ,
                          const float* __restrict__ WK) {
    __shared__ float4 swq0[256], swq1[256], swk0[256], swk1[256];
    const float4* WQ4 = (const float4*)WQ;
    const float4* WK4 = (const float4*)WK;
    int tid = threadIdx.x;
    swq0[tid] = WQ4[tid];
    swq1[tid] = WQ4[256 + tid];
    swk0[tid] = WK4[tid];
    swk1[tid] = WK4[256 + tid];
    __syncthreads();

    int warp = tid >> 5, lane = tid & 31;
    int row = blockIdx.x * 8 + warp;           // b*T + t
    const float4* x4 = (const float4*)x + (size_t)row * 256;

    float q0 = 0.f, q1 = 0.f, k0 = 0.f, k1 = 0.f;
#pragma unroll
    for (int j = 0; j < 8; ++j) {
        int d = lane + j * 32;
        float4 xv = x4[d];
        float4 a = swq0[d], b = swq1[d], c = swk0[d], e = swk1[d];
        q0 += xv.x*a.x + xv.y*a.y + xv.z*a.z + xv.w*a.w;
        q1 += xv.x*b.x + xv.y*b.y + xv.z*b.z + xv.w*b.w;
        k0 += xv.x*c.x + xv.y*c.y + xv.z*c.z + xv.w*c.w;
        k1 += xv.x*e.x + xv.y*e.y + xv.z*e.z + xv.w*e.w;
    }
#pragma unroll
    for (int off = 16; off; off >>= 1) {
        q0 += __shfl_xor_sync(FULL, q0, off);
        q1 += __shfl_xor_sync(FULL, q1, off);
        k0 += __shfl_xor_sync(FULL, k0, off);
        k1 += __shfl_xor_sync(FULL, k1, off);
    }
    if (lane == 0) {
        g_Q[row] = make_float2(q0, q1);
        g_K[row] = make_float2(k0, k1);
        g_mark[row] = 0;
        g_best64[row] = 0ull;                  // < any real score encoding
        if (row == 0) g_count = 0;
    }
}

// ---------------- kernel 2: argmax, tile x chunk units ----------------
// Unit = (128-t tile, 1024-s chunk). 80 units/batch, grid (80, BB), 128 thr.
// Merge via atomicMax of (ordered(score)<<32)|~s  -> max score, min s on tie.
__global__ void __launch_bounds__(128) argmax_kernel() {
    __shared__ float2 ks[1024];    // 8 KB
    int b = blockIdx.y;
    int u = blockIdx.x, g = 0, base = 0;
    while (u >= base + 8 * (g + 1)) { base += 8 * (g + 1); ++g; }
    int r = u - base;
    int ti = g * 8 + r / (g + 1);
    int chunk = r % (g + 1);
    int t0 = ti * 128, s0 = chunk * 1024;

    const float4* K4 = (const float4*)(g_K + b * TT + s0);
#pragma unroll
    for (int j = 0; j < 4; ++j)
        ((float4*)ks)[threadIdx.x + j * 128] = K4[threadIdx.x + j * 128];
    __syncthreads();

    int t = t0 + threadIdx.x;
    float2 q = g_Q[b * TT + t];
    int s_limit = t - s0 + 1;
    if (s_limit > 1024) s_limit = 1024;

    float best = -CUDART_INF_F;
    int bi = 0;
    for (int s = 0; s < s_limit; ++s) {        // ascending + strict > = first occ.
        float2 k = ks[s];
        float sc = k.x * q.x + k.y * q.y;
        if (sc > best) { best = sc; bi = s0 + s; }
    }
    unsigned long long enc =
        ((unsigned long long)ord_f32(best) << 32) | (unsigned)(~bi);
    atomicMax(&g_best64[b * TT + t], enc);
}

// ---------------- kernel 2b: decode argmax + build unique list -------------
__global__ void decode_kernel() {
    int i = blockIdx.x * 256 + threadIdx.x;
    if (i >= NROW) return;
    unsigned long long enc = g_best64[i];
    int s = (int)(~(unsigned)(enc & 0xffffffffull));
    int src = (i & ~(TT - 1)) | s;
    g_idx[i] = src;
    if (atomicExch(&g_mark[src], 1) == 0) {
        int p = atomicAdd(&g_count, 1);
        g_list[p] = src;
        g_slot[src] = p;                       // read only by later kernels
    }
}

// ---------------- kernel 3: V rows, row-group x e-tile ----------------
// Item = (group of 8 unique rows, 16-e tile): ceil(cnt/8)*64 items over 512
// blocks. Block stages 8 x rows in smem (32 KB); warp owns 2 e-rows of W_V,
// keeps 16 accumulators (8 rows x 2 e): per j-step 2 global float4 loads
// amortized over 8 rows + 64 FFMAs. W_V traffic total = 32 MB.
#define RG 8
__global__ void __launch_bounds__(256) vrows_kernel(const float* __restrict__ WV,
                                                    const float* __restrict__ x) {
    __shared__ float4 xs[RG * 256];            // 32 KB
    int cnt = g_count;
    int ngrp = (cnt + RG - 1) / RG;
    int items = ngrp * 64;                     // 64 e-tiles of 16
    int warp = threadIdx.x >> 5, lane = threadIdx.x & 31;

    for (int it = blockIdx.x; it < items; it += gridDim.x) {
        int grp  = it >> 6;                    // / 64
        int tile = it & 63;
        int ui0  = grp * RG;

        __syncthreads();                       // protect xs reuse
        {
            int rr = threadIdx.x >> 5;         // warp w loads row w
            int ui = ui0 + rr;
            int row = g_list[(ui < cnt) ? ui : 0];
            const float4* xr = (const float4*)x + (size_t)row * 256;
#pragma unroll
            for (int j = 0; j < 8; ++j)
                xs[rr * 256 + lane + j * 32] = xr[lane + j * 32];
        }
        __syncthreads();

        int e0 = tile * 16 + warp * 2;
        const float4* w0p = (const float4*)WV + (size_t)(e0 + 0) * 256;
        const float4* w1p = (const float4*)WV + (size_t)(e0 + 1) * 256;

        float a0[RG], a1[RG];
#pragma unroll
        for (int r = 0; r < RG; ++r) { a0[r] = 0.f; a1[r] = 0.f; }

#pragma unroll
        for (int j = 0; j < 8; ++j) {
            int d = lane + j * 32;
            float4 w0 = __ldg(&w0p[d]);
            float4 w1 = __ldg(&w1p[d]);
#pragma unroll
            for (int r = 0; r < RG; ++r) {
                float4 xv = xs[r * 256 + d];
                a0[r] += w0.x*xv.x + w0.y*xv.y + w0.z*xv.z + w0.w*xv.w;
                a1[r] += w1.x*xv.x + w1.y*xv.y + w1.z*xv.z + w1.w*xv.w;
            }
        }
#pragma unroll
        for (int off = 16; off; off >>= 1) {
#pragma unroll
            for (int r = 0; r < RG; ++r) {
                a0[r] += __shfl_xor_sync(FULL, a0[r], off);
                a1[r] += __shfl_xor_sync(FULL, a1[r], off);
            }
        }
        if (lane == 0) {
#pragma unroll
            for (int r = 0; r < RG; ++r) {
                int ui = ui0 + r;
                if (ui < cnt) {
                    float* dst = g_Vc + (size_t)ui * DD + e0;
                    dst[0] = a0[r];
                    dst[1] = a1[r];
                }
            }
        }
    }
}

// ---------------- kernel 4: gather to output ----------------
// Warp copies one 4KB row from compact (L2-resident) V; streaming stores.
__global__ void gather_kernel(float* __restrict__ out) {
    int warp = threadIdx.x >> 5, lane = threadIdx.x & 31;
    int r = blockIdx.x * 8 + warp;          // destination row b*T + t
    int slot = g_slot[g_idx[r]];
    const float4* v4 = (const float4*)g_Vc + (size_t)slot * 256;
    float4* o4 = (float4*)out + (size_t)r * 256;
#pragma unroll
    for (int j = 0; j < 8; ++j) {
        float4 v = __ldg(&v4[lane + j * 32]);
        __stcs(&o4[lane + j * 32], v);
    }
}

extern "C" void kernel_launch(void* const* d_in, const int* in_sizes, int n_in,
                              void* d_out, int out_size) {
    const float* x  = (const float*)d_in[0];
    const float* WQ = (const float*)d_in[1];
    const float* WK = (const float*)d_in[2];
    const float* WV = (const float*)d_in[3];
    float* out = (float*)d_out;

    qk_kernel<<<NROW / 8, 256>>>(x, WQ, WK);
    argmax_kernel<<<dim3(80, BB), 128>>>();
    decode_kernel<<<NROW / 256, 256>>>();
    vrows_kernel<<<512, 256>>>(WV, x);
    gather_kernel<<<NROW / 8, 256>>>(out);
}

// round 7
// speedup vs baseline: 1.3560x; 1.0646x over previous
#include <cuda_runtime.h>
#include <math_constants.h>

#define BB 4
#define TT 4096
#define DD 1024
#define NROW (BB*TT)          // 16384

// ---- scratch (device globals: no allocations allowed) ----
__device__ float2 g_Q[NROW];
__device__ float2 g_K[NROW];
__device__ unsigned long long g_best64[NROW]; // (ordered(score)<<32)|~s
__device__ int    g_idx[NROW];      // flattened source row b*T + argmax_s
__device__ int    g_mark[NROW];
__device__ int    g_slot[NROW];     // src row -> compact slot
__device__ int    g_list[NROW];
__device__ int    g_count;
__device__ float  g_Vc[(size_t)NROW * DD];  // compact V rows (slot-major)

static const unsigned FULL = 0xffffffffu;

__device__ __forceinline__ unsigned ord_f32(float x) {
    unsigned u = __float_as_uint(x);
    return (u & 0x80000000u) ? ~u : (u | 0x80000000u);
}

// ---------------- kernel 1: Q,K projection (+ fused scratch init) ----------
__global__ void qk_kernel(const float* __restrict__ x,
                          const float* __restrict__ WQ,
                          const float* __restrict__ WK) {
    __shared__ float4 swq0[256], swq1[256], swk0[256], swk1[256];
    const float4* WQ4 = (const float4*)WQ;
    const float4* WK4 = (const float4*)WK;
    int tid = threadIdx.x;
    swq0[tid] = WQ4[tid];
    swq1[tid] = WQ4[256 + tid];
    swk0[tid] = WK4[tid];
    swk1[tid] = WK4[256 + tid];
    __syncthreads();

    int warp = tid >> 5, lane = tid & 31;
    int row = blockIdx.x * 8 + warp;           // b*T + t
    const float4* x4 = (const float4*)x + (size_t)row * 256;

    float q0 = 0.f, q1 = 0.f, k0 = 0.f, k1 = 0.f;
#pragma unroll
    for (int j = 0; j < 8; ++j) {
        int d = lane + j * 32;
        float4 xv = x4[d];
        float4 a = swq0[d], b = swq1[d], c = swk0[d], e = swk1[d];
        q0 += xv.x*a.x + xv.y*a.y + xv.z*a.z + xv.w*a.w;
        q1 += xv.x*b.x + xv.y*b.y + xv.z*b.z + xv.w*b.w;
        k0 += xv.x*c.x + xv.y*c.y + xv.z*c.z + xv.w*c.w;
        k1 += xv.x*e.x + xv.y*e.y + xv.z*e.z + xv.w*e.w;
    }
#pragma unroll
    for (int off = 16; off; off >>= 1) {
        q0 += __shfl_xor_sync(FULL, q0, off);
        q1 += __shfl_xor_sync(FULL, q1, off);
        k0 += __shfl_xor_sync(FULL, k0, off);
        k1 += __shfl_xor_sync(FULL, k1, off);
    }
    if (lane == 0) {
        g_Q[row] = make_float2(q0, q1);
        g_K[row] = make_float2(k0, k1);
        g_mark[row] = 0;
        g_best64[row] = 0ull;                  // < any real score encoding
        if (row == 0) g_count = 0;
    }
}

// ---------------- kernel 2: argmax, tile x chunk units ----------------
// Unit = (128-t tile, 1024-s chunk). 80 units/batch, grid (80, BB), 128 thr.
// Merge via atomicMax of (ordered(score)<<32)|~s  -> max score, min s on tie.
__global__ void __launch_bounds__(128) argmax_kernel() {
    __shared__ float2 ks[1024];    // 8 KB
    int b = blockIdx.y;
    int u = blockIdx.x, g = 0, base = 0;
    while (u >= base + 8 * (g + 1)) { base += 8 * (g + 1); ++g; }
    int r = u - base;
    int ti = g * 8 + r / (g + 1);
    int chunk = r % (g + 1);
    int t0 = ti * 128, s0 = chunk * 1024;

    const float4* K4 = (const float4*)(g_K + b * TT + s0);
#pragma unroll
    for (int j = 0; j < 4; ++j)
        ((float4*)ks)[threadIdx.x + j * 128] = K4[threadIdx.x + j * 128];
    __syncthreads();

    int t = t0 + threadIdx.x;
    float2 q = g_Q[b * TT + t];
    int s_limit = t - s0 + 1;
    if (s_limit > 1024) s_limit = 1024;

    float best = -CUDART_INF_F;
    int bi = 0;
    for (int s = 0; s < s_limit; ++s) {        // ascending + strict > = first occ.
        float2 k = ks[s];
        float sc = k.x * q.x + k.y * q.y;
        if (sc > best) { best = sc; bi = s0 + s; }
    }
    unsigned long long enc =
        ((unsigned long long)ord_f32(best) << 32) | (unsigned)(~bi);
    atomicMax(&g_best64[b * TT + t], enc);
}

// ---------------- kernel 2b: decode argmax + build unique list -------------
__global__ void decode_kernel() {
    int i = blockIdx.x * 256 + threadIdx.x;
    if (i >= NROW) return;
    unsigned long long enc = g_best64[i];
    int s = (int)(~(unsigned)(enc & 0xffffffffull));
    int src = (i & ~(TT - 1)) | s;
    g_idx[i] = src;
    if (atomicExch(&g_mark[src], 1) == 0) {
        int p = atomicAdd(&g_count, 1);
        g_list[p] = src;
        g_slot[src] = p;                       // read only by later kernels
    }
}

// ---------------- kernel 3: V rows, 8 rows x 4 e per warp ----------------
// Item = (8-row group, 32-e tile): ceil(cnt/8)*32 items over 444 blocks.
// Block stages 8 x rows in smem (32 KB). Warp owns 4 e-rows: per j-step
// 8 LDS.128 + 4 LDG.128 + 128 FFMA (91% FFMA). Epilogue: 31-SHFL
// multi-value butterfly reduces all 32 accumulators; lane l ends with the
// full sum for pair l (row=l>>2, e=l&3) and issues one STG.
#define RG 8
__global__ void __launch_bounds__(256) vrows_kernel(const float* __restrict__ WV,
                                                    const float* __restrict__ x) {
    __shared__ float4 xs[RG * 256];            // 32 KB
    int cnt = g_count;
    int ngrp = (cnt + RG - 1) / RG;
    int items = ngrp * 32;                     // 32 e-tiles of 32
    int warp = threadIdx.x >> 5, lane = threadIdx.x & 31;

    for (int it = blockIdx.x; it < items; it += gridDim.x) {
        int grp  = it >> 5;                    // / 32
        int tile = it & 31;
        int ui0  = grp * RG;

        __syncthreads();                       // protect xs reuse
        {
            int ui = ui0 + warp;               // warp w loads row w
            int row = g_list[(ui < cnt) ? ui : 0];
            const float4* xr = (const float4*)x + (size_t)row * 256;
#pragma unroll
            for (int j = 0; j < 8; ++j)
                xs[warp * 256 + lane + j * 32] = xr[lane + j * 32];
        }
        __syncthreads();

        int e0 = tile * 32 + warp * 4;
        const float4* wp0 = (const float4*)WV + (size_t)(e0 + 0) * 256;
        const float4* wp1 = (const float4*)WV + (size_t)(e0 + 1) * 256;
        const float4* wp2 = (const float4*)WV + (size_t)(e0 + 2) * 256;
        const float4* wp3 = (const float4*)WV + (size_t)(e0 + 3) * 256;

        float a[32];                           // a[r*4+e]
#pragma unroll
        for (int k = 0; k < 32; ++k) a[k] = 0.f;

#pragma unroll
        for (int j = 0; j < 8; ++j) {
            int d = lane + j * 32;
            float4 w0 = __ldg(&wp0[d]);
            float4 w1 = __ldg(&wp1[d]);
            float4 w2 = __ldg(&wp2[d]);
            float4 w3 = __ldg(&wp3[d]);
#pragma unroll
            for (int r = 0; r < RG; ++r) {
                float4 xv = xs[r * 256 + d];
                a[r*4+0] += w0.x*xv.x + w0.y*xv.y + w0.z*xv.z + w0.w*xv.w;
                a[r*4+1] += w1.x*xv.x + w1.y*xv.y + w1.z*xv.z + w1.w*xv.w;
                a[r*4+2] += w2.x*xv.x + w2.y*xv.y + w2.z*xv.z + w2.w*xv.w;
                a[r*4+3] += w3.x*xv.x + w3.y*xv.y + w3.z*xv.z + w3.w*xv.w;
            }
        }

        // multi-value butterfly: 31 SHFL total; lane l ends with pair l.
#pragma unroll
        for (int off = 16; off; off >>= 1) {
#pragma unroll
            for (int i = 0; i < off; ++i) {
                float lo = a[i], hi = a[i + off];
                float mine = (lane & off) ? hi : lo;
                float send = (lane & off) ? lo : hi;
                float other = __shfl_xor_sync(FULL, send, off);
                a[i] = mine + other;
            }
        }

        int r = lane >> 2, e = lane & 3;
        int ui = ui0 + r;
        if (ui < cnt)
            g_Vc[(size_t)ui * DD + e0 + e] = a[0];
    }
}

// ---------------- kernel 4: gather to output ----------------
// Warp copies one 4KB row from compact (L2-resident) V; streaming stores.
__global__ void gather_kernel(float* __restrict__ out) {
    int warp = threadIdx.x >> 5, lane = threadIdx.x & 31;
    int r = blockIdx.x * 8 + warp;          // destination row b*T + t
    int slot = g_slot[g_idx[r]];
    const float4* v4 = (const float4*)g_Vc + (size_t)slot * 256;
    float4* o4 = (float4*)out + (size_t)r * 256;
#pragma unroll
    for (int j = 0; j < 8; ++j) {
        float4 v = __ldg(&v4[lane + j * 32]);
        __stcs(&o4[lane + j * 32], v);
    }
}

extern "C" void kernel_launch(void* const* d_in, const int* in_sizes, int n_in,
                              void* d_out, int out_size) {
    const float* x  = (const float*)d_in[0];
    const float* WQ = (const float*)d_in[1];
    const float* WK = (const float*)d_in[2];
    const float* WV = (const float*)d_in[3];
    float* out = (float*)d_out;

    qk_kernel<<<NROW / 8, 256>>>(x, WQ, WK);
    argmax_kernel<<<dim3(80, BB), 128>>>();
    decode_kernel<<<NROW / 256, 256>>>();
    vrows_kernel<<<444, 256>>>(WV, x);
    gather_kernel<<<NROW / 8, 256>>>(out);
}